// round 1
// baseline (speedup 1.0000x reference)
#include <cuda_runtime.h>

#define NNODES 100000
#define NEDGES 1600000
#define F 32          // NODE_IN = EDGE_IN = NODE_OUT = EDGE_OUT
#define HID 64
#define EIN 96        // edge MLP input dim
#define NIN 64        // node MLP input dim
#define XPAD 129      // 128 cols + 1 pad for bank-conflict-free shared

// scratch for segment_sum (12.8 MB) — __device__ global, no allocation
__device__ float g_agg[NNODES * F];

__global__ void zero_agg_kernel() {
    int i = blockIdx.x * blockDim.x + threadIdx.x;
    if (i < NNODES * F) g_agg[i] = 0.0f;
}

// ---------------------------------------------------------------------------
// Edge kernel: u_ef[e] = MLP96(concat(nf[src], nf[dst], ef)); atomicAdd into agg[dst]
// ---------------------------------------------------------------------------
__global__ __launch_bounds__(128)
void edge_kernel(const float* __restrict__ nf, const float* __restrict__ ef,
                 const int* __restrict__ src, const int* __restrict__ dst,
                 const float* __restrict__ W1, const float* __restrict__ b1,
                 const float* __restrict__ W2, const float* __restrict__ b2,
                 const float* __restrict__ W3, const float* __restrict__ b3,
                 float* __restrict__ u_ef)
{
    extern __shared__ float smem[];
    float* xs  = smem;                 // [EIN][XPAD] transposed inputs
    float* W1s = xs  + EIN * XPAD;     // [96*64]
    float* W2s = W1s + EIN * HID;      // [64*64]
    float* W3s = W2s + HID * HID;      // [64*32]
    float* b1s = W3s + HID * F;
    float* b2s = b1s + HID;
    float* b3s = b2s + HID;

    const int tid  = threadIdx.x;
    const int lane = tid & 31;
    const int warp = tid >> 5;

    for (int i = tid; i < EIN * HID; i += 128) W1s[i] = W1[i];
    for (int i = tid; i < HID * HID; i += 128) W2s[i] = W2[i];
    for (int i = tid; i < HID * F;   i += 128) W3s[i] = W3[i];
    if (tid < HID) { b1s[tid] = b1[tid]; b2s[tid] = b2[tid]; }
    if (tid < F)   { b3s[tid] = b3[tid]; }

    const int ebase = blockIdx.x * 128;          // NEDGES % 128 == 0
    const int my_e  = ebase + tid;
    const int si = src[my_e];
    const int di = dst[my_e];

    // cooperative gather: each warp fills its 32 columns, 128B-coalesced rows
    #pragma unroll 4
    for (int i = 0; i < 32; i++) {
        int srow = __shfl_sync(0xffffffffu, si, i);
        int drow = __shfl_sync(0xffffffffu, di, i);
        int col  = warp * 32 + i;
        xs[lane * XPAD + col]        = nf[srow * F + lane];
        xs[(32 + lane) * XPAD + col] = nf[drow * F + lane];
        xs[(64 + lane) * XPAD + col] = ef[(ebase + col) * F + lane];
    }
    __syncthreads();

    // layer 1: 96 -> 64
    float h1[HID];
    #pragma unroll
    for (int j = 0; j < HID; j++) h1[j] = b1s[j];
    #pragma unroll 2
    for (int k = 0; k < EIN; k++) {
        float xk = xs[k * XPAD + tid];
        #pragma unroll
        for (int j = 0; j < HID; j++) h1[j] = fmaf(xk, W1s[k * HID + j], h1[j]);
    }
    #pragma unroll
    for (int j = 0; j < HID; j++) h1[j] = fmaxf(h1[j], 0.0f);

    // layer 2: 64 -> 64
    float h2[HID];
    #pragma unroll
    for (int j = 0; j < HID; j++) h2[j] = b2s[j];
    #pragma unroll 2
    for (int k = 0; k < HID; k++) {
        float xk = h1[k];
        #pragma unroll
        for (int j = 0; j < HID; j++) h2[j] = fmaf(xk, W2s[k * HID + j], h2[j]);
    }
    #pragma unroll
    for (int j = 0; j < HID; j++) h2[j] = fmaxf(h2[j], 0.0f);

    // layer 3: 64 -> 32
    float o[F];
    #pragma unroll
    for (int j = 0; j < F; j++) o[j] = b3s[j];
    #pragma unroll 2
    for (int k = 0; k < HID; k++) {
        float xk = h2[k];
        #pragma unroll
        for (int j = 0; j < F; j++) o[j] = fmaf(xk, W3s[k * F + j], o[j]);
    }

    float* out_row = u_ef + (size_t)my_e * F;
    float* agg_row = g_agg + (size_t)di * F;
    #pragma unroll
    for (int j = 0; j < F; j += 4) {
        float4 v;
        v.x = fmaxf(o[j + 0], 0.0f);
        v.y = fmaxf(o[j + 1], 0.0f);
        v.z = fmaxf(o[j + 2], 0.0f);
        v.w = fmaxf(o[j + 3], 0.0f);
        *reinterpret_cast<float4*>(out_row + j) = v;
        atomicAdd(agg_row + j + 0, v.x);
        atomicAdd(agg_row + j + 1, v.y);
        atomicAdd(agg_row + j + 2, v.z);
        atomicAdd(agg_row + j + 3, v.w);
    }
}

// ---------------------------------------------------------------------------
// Node kernel: u_nf[n] = MLP64(concat(nf[n], agg[n]))
// ---------------------------------------------------------------------------
__global__ __launch_bounds__(128)
void node_kernel(const float* __restrict__ nf,
                 const float* __restrict__ W1, const float* __restrict__ b1,
                 const float* __restrict__ W2, const float* __restrict__ b2,
                 const float* __restrict__ W3, const float* __restrict__ b3,
                 float* __restrict__ u_nf)
{
    extern __shared__ float smem[];
    float* xs  = smem;                 // [NIN][XPAD]
    float* W1s = xs  + NIN * XPAD;     // [64*64]
    float* W2s = W1s + NIN * HID;      // [64*64]
    float* W3s = W2s + HID * HID;      // [64*32]
    float* b1s = W3s + HID * F;
    float* b2s = b1s + HID;
    float* b3s = b2s + HID;

    const int tid  = threadIdx.x;
    const int lane = tid & 31;
    const int warp = tid >> 5;

    for (int i = tid; i < NIN * HID; i += 128) W1s[i] = W1[i];
    for (int i = tid; i < HID * HID; i += 128) W2s[i] = W2[i];
    for (int i = tid; i < HID * F;   i += 128) W3s[i] = W3[i];
    if (tid < HID) { b1s[tid] = b1[tid]; b2s[tid] = b2[tid]; }
    if (tid < F)   { b3s[tid] = b3[tid]; }

    const int nbase = blockIdx.x * 128;
    #pragma unroll 4
    for (int i = 0; i < 32; i++) {
        int n = nbase + warp * 32 + i;
        if (n < NNODES) {
            int col = warp * 32 + i;
            xs[lane * XPAD + col]        = nf[n * F + lane];
            xs[(32 + lane) * XPAD + col] = g_agg[n * F + lane];
        }
    }
    __syncthreads();

    const int my_n = nbase + tid;
    if (my_n >= NNODES) return;

    float h1[HID];
    #pragma unroll
    for (int j = 0; j < HID; j++) h1[j] = b1s[j];
    #pragma unroll 2
    for (int k = 0; k < NIN; k++) {
        float xk = xs[k * XPAD + tid];
        #pragma unroll
        for (int j = 0; j < HID; j++) h1[j] = fmaf(xk, W1s[k * HID + j], h1[j]);
    }
    #pragma unroll
    for (int j = 0; j < HID; j++) h1[j] = fmaxf(h1[j], 0.0f);

    float h2[HID];
    #pragma unroll
    for (int j = 0; j < HID; j++) h2[j] = b2s[j];
    #pragma unroll 2
    for (int k = 0; k < HID; k++) {
        float xk = h1[k];
        #pragma unroll
        for (int j = 0; j < HID; j++) h2[j] = fmaf(xk, W2s[k * HID + j], h2[j]);
    }
    #pragma unroll
    for (int j = 0; j < HID; j++) h2[j] = fmaxf(h2[j], 0.0f);

    float o[F];
    #pragma unroll
    for (int j = 0; j < F; j++) o[j] = b3s[j];
    #pragma unroll 2
    for (int k = 0; k < HID; k++) {
        float xk = h2[k];
        #pragma unroll
        for (int j = 0; j < F; j++) o[j] = fmaf(xk, W3s[k * F + j], o[j]);
    }

    float* out_row = u_nf + (size_t)my_n * F;
    #pragma unroll
    for (int j = 0; j < F; j += 4) {
        float4 v;
        v.x = fmaxf(o[j + 0], 0.0f);
        v.y = fmaxf(o[j + 1], 0.0f);
        v.z = fmaxf(o[j + 2], 0.0f);
        v.w = fmaxf(o[j + 3], 0.0f);
        *reinterpret_cast<float4*>(out_row + j) = v;
    }
}

extern "C" void kernel_launch(void* const* d_in, const int* in_sizes, int n_in,
                              void* d_out, int out_size)
{
    const float* nf  = (const float*)d_in[0];
    const float* ef  = (const float*)d_in[1];
    const int*   src = (const int*)  d_in[2];
    const int*   dst = (const int*)  d_in[3];
    const float* eW1 = (const float*)d_in[4];
    const float* eb1 = (const float*)d_in[5];
    const float* eW2 = (const float*)d_in[6];
    const float* eb2 = (const float*)d_in[7];
    const float* eW3 = (const float*)d_in[8];
    const float* eb3 = (const float*)d_in[9];
    const float* nW1 = (const float*)d_in[10];
    const float* nb1 = (const float*)d_in[11];
    const float* nW2 = (const float*)d_in[12];
    const float* nb2 = (const float*)d_in[13];
    const float* nW3 = (const float*)d_in[14];
    const float* nb3 = (const float*)d_in[15];

    float* out  = (float*)d_out;
    float* u_nf = out;                         // [NNODES, 32] first
    float* u_ef = out + (size_t)NNODES * F;    // [NEDGES, 32] second

    const int edge_smem = (EIN * XPAD + EIN * HID + HID * HID + HID * F
                           + HID + HID + F) * (int)sizeof(float);   // ~99.3 KB
    const int node_smem = (NIN * XPAD + NIN * HID + HID * HID + HID * F
                           + HID + HID + F) * (int)sizeof(float);   // ~74.6 KB

    cudaFuncSetAttribute(edge_kernel, cudaFuncAttributeMaxDynamicSharedMemorySize, edge_smem);
    cudaFuncSetAttribute(node_kernel, cudaFuncAttributeMaxDynamicSharedMemorySize, node_smem);

    zero_agg_kernel<<<(NNODES * F + 255) / 256, 256>>>();

    edge_kernel<<<NEDGES / 128, 128, edge_smem>>>(
        nf, ef, src, dst, eW1, eb1, eW2, eb2, eW3, eb3, u_ef);

    node_kernel<<<(NNODES + 127) / 128, 128, node_smem>>>(
        nf, nW1, nb1, nW2, nb2, nW3, nb3, u_nf);
}

// round 2
// speedup vs baseline: 3.4331x; 3.4331x over previous
#include <cuda_runtime.h>

#define NNODES 100000
#define NEDGES 1600000
#define F 32
#define HID 64
#define XL 132        // xs row length (floats): 4-aligned for LDS.128, stride 132%32=4 banks on gather
#define HL 68         // hs row length (floats): 4-aligned

// scratch for segment_sum (12.8 MB)
__device__ float g_agg[NNODES * F];

__global__ void zero_agg_kernel() {
    int i = blockIdx.x * blockDim.x + threadIdx.x;
    if (i < NNODES * F) g_agg[i] = 0.0f;
}

// ---------------------------------------------------------------------------
// Edge kernel: fused 3-layer MLP, register-blocked 8x4 per thread.
// CTA = 128 edges, 256 threads (tx 0..15 -> 4 output cols, ty 0..15 -> 8 rows)
// ---------------------------------------------------------------------------
__global__ __launch_bounds__(256)
void edge_kernel(const float* __restrict__ nf, const float* __restrict__ ef,
                 const int* __restrict__ src, const int* __restrict__ dst,
                 const float* __restrict__ W1, const float* __restrict__ b1,
                 const float* __restrict__ W2, const float* __restrict__ b2,
                 const float* __restrict__ W3, const float* __restrict__ b3,
                 float* __restrict__ u_ef)
{
    extern __shared__ float smem[];
    float* xs  = smem;                 // region: max(96*XL=12672, 128*HL=8704)
    float* W1s = smem + 96 * XL;       // [96][64]
    float* W2s = W1s + 96 * HID;       // [64][64]
    float* W3s = W2s + HID * HID;      // [64][32]
    float* b1s = W3s + HID * F;
    float* b2s = b1s + HID;
    float* b3s = b2s + HID;

    const int tid  = threadIdx.x;
    const int lane = tid & 31;
    const int warp = tid >> 5;
    const int tx   = tid & 15;         // output-col group
    const int ty   = tid >> 4;         // row group (8 rows each)

    for (int i = tid; i < 96 * HID;  i += 256) W1s[i] = W1[i];
    for (int i = tid; i < HID * HID; i += 256) W2s[i] = W2[i];
    for (int i = tid; i < HID * F;   i += 256) W3s[i] = W3[i];
    if (tid < HID) { b1s[tid] = b1[tid]; b2s[tid] = b2[tid]; }
    if (tid < F)   { b3s[tid] = b3[tid]; }

    const int ebase = blockIdx.x * 128;

    // gather inputs transposed: xs[k][edge]
    for (int i = warp; i < 128; i += 8) {
        int e = ebase + i;
        int s = src[e];
        int d = dst[e];
        xs[lane * XL + i]        = nf[s * F + lane];
        xs[(32 + lane) * XL + i] = nf[d * F + lane];
        xs[(64 + lane) * XL + i] = ef[(size_t)e * F + lane];
    }
    __syncthreads();

    // ---- layer 1: K=96, N=64 ----
    float acc[32];
    #pragma unroll
    for (int r = 0; r < 8; r++)
        #pragma unroll
        for (int c = 0; c < 4; c++) acc[r * 4 + c] = b1s[tx * 4 + c];

    #pragma unroll 4
    for (int k = 0; k < 96; k++) {
        float4 b  = *(const float4*)&W1s[k * HID + tx * 4];
        float4 a0 = *(const float4*)&xs[k * XL + ty * 8];
        float4 a1 = *(const float4*)&xs[k * XL + ty * 8 + 4];
        float a[8] = {a0.x, a0.y, a0.z, a0.w, a1.x, a1.y, a1.z, a1.w};
        #pragma unroll
        for (int r = 0; r < 8; r++) {
            acc[r * 4 + 0] = fmaf(a[r], b.x, acc[r * 4 + 0]);
            acc[r * 4 + 1] = fmaf(a[r], b.y, acc[r * 4 + 1]);
            acc[r * 4 + 2] = fmaf(a[r], b.z, acc[r * 4 + 2]);
            acc[r * 4 + 3] = fmaf(a[r], b.w, acc[r * 4 + 3]);
        }
    }
    __syncthreads();                   // all layer-1 reads of xs done

    float* hs = xs;                    // reuse region as hs[128][HL]
    #pragma unroll
    for (int r = 0; r < 8; r++) {
        float4 v;
        v.x = fmaxf(acc[r * 4 + 0], 0.0f);
        v.y = fmaxf(acc[r * 4 + 1], 0.0f);
        v.z = fmaxf(acc[r * 4 + 2], 0.0f);
        v.w = fmaxf(acc[r * 4 + 3], 0.0f);
        *(float4*)&hs[(ty * 8 + r) * HL + tx * 4] = v;
    }
    __syncthreads();

    // ---- layer 2: K=64, N=64 ----
    #pragma unroll
    for (int r = 0; r < 8; r++)
        #pragma unroll
        for (int c = 0; c < 4; c++) acc[r * 4 + c] = b2s[tx * 4 + c];

    #pragma unroll 2
    for (int k = 0; k < HID; k++) {
        float4 b = *(const float4*)&W2s[k * HID + tx * 4];
        float a[8];
        #pragma unroll
        for (int r = 0; r < 8; r++) a[r] = hs[(ty * 8 + r) * HL + k];
        #pragma unroll
        for (int r = 0; r < 8; r++) {
            acc[r * 4 + 0] = fmaf(a[r], b.x, acc[r * 4 + 0]);
            acc[r * 4 + 1] = fmaf(a[r], b.y, acc[r * 4 + 1]);
            acc[r * 4 + 2] = fmaf(a[r], b.z, acc[r * 4 + 2]);
            acc[r * 4 + 3] = fmaf(a[r], b.w, acc[r * 4 + 3]);
        }
    }
    __syncthreads();                   // all layer-2 reads done

    #pragma unroll
    for (int r = 0; r < 8; r++) {
        float4 v;
        v.x = fmaxf(acc[r * 4 + 0], 0.0f);
        v.y = fmaxf(acc[r * 4 + 1], 0.0f);
        v.z = fmaxf(acc[r * 4 + 2], 0.0f);
        v.w = fmaxf(acc[r * 4 + 3], 0.0f);
        *(float4*)&hs[(ty * 8 + r) * HL + tx * 4] = v;
    }
    __syncthreads();

    // ---- layer 3: K=64, N=32 ----
    float acc3[16];
    #pragma unroll
    for (int r = 0; r < 8; r++) {
        acc3[r * 2 + 0] = b3s[tx * 2 + 0];
        acc3[r * 2 + 1] = b3s[tx * 2 + 1];
    }
    #pragma unroll 2
    for (int k = 0; k < HID; k++) {
        float2 b = *(const float2*)&W3s[k * F + tx * 2];
        float a[8];
        #pragma unroll
        for (int r = 0; r < 8; r++) a[r] = hs[(ty * 8 + r) * HL + k];
        #pragma unroll
        for (int r = 0; r < 8; r++) {
            acc3[r * 2 + 0] = fmaf(a[r], b.x, acc3[r * 2 + 0]);
            acc3[r * 2 + 1] = fmaf(a[r], b.y, acc3[r * 2 + 1]);
        }
    }

    // epilogue: relu, store u_ef, atomic-accumulate into g_agg[dst]
    #pragma unroll
    for (int r = 0; r < 8; r++) {
        int e = ebase + ty * 8 + r;
        float2 v;
        v.x = fmaxf(acc3[r * 2 + 0], 0.0f);
        v.y = fmaxf(acc3[r * 2 + 1], 0.0f);
        *(float2*)&u_ef[(size_t)e * F + tx * 2] = v;
        int d = dst[e];
        atomicAdd(&g_agg[d * F + tx * 2 + 0], v.x);
        atomicAdd(&g_agg[d * F + tx * 2 + 1], v.y);
    }
}

// ---------------------------------------------------------------------------
// Node kernel: same structure, K1=64 (nf || agg)
// ---------------------------------------------------------------------------
__global__ __launch_bounds__(256)
void node_kernel(const float* __restrict__ nf,
                 const float* __restrict__ W1, const float* __restrict__ b1,
                 const float* __restrict__ W2, const float* __restrict__ b2,
                 const float* __restrict__ W3, const float* __restrict__ b3,
                 float* __restrict__ u_nf)
{
    extern __shared__ float smem[];
    float* xs  = smem;                 // region: max(64*XL=8448, 128*HL=8704) = 8704
    float* W1s = smem + 128 * HL;
    float* W2s = W1s + HID * HID;
    float* W3s = W2s + HID * HID;
    float* b1s = W3s + HID * F;
    float* b2s = b1s + HID;
    float* b3s = b2s + HID;

    const int tid  = threadIdx.x;
    const int lane = tid & 31;
    const int warp = tid >> 5;
    const int tx   = tid & 15;
    const int ty   = tid >> 4;

    for (int i = tid; i < HID * HID; i += 256) W1s[i] = W1[i];
    for (int i = tid; i < HID * HID; i += 256) W2s[i] = W2[i];
    for (int i = tid; i < HID * F;   i += 256) W3s[i] = W3[i];
    if (tid < HID) { b1s[tid] = b1[tid]; b2s[tid] = b2[tid]; }
    if (tid < F)   { b3s[tid] = b3[tid]; }

    const int nbase = blockIdx.x * 128;

    for (int i = warp; i < 128; i += 8) {
        int n = nbase + i;
        float v1 = 0.0f, v2 = 0.0f;
        if (n < NNODES) {
            v1 = nf[(size_t)n * F + lane];
            v2 = g_agg[(size_t)n * F + lane];
        }
        xs[lane * XL + i]        = v1;
        xs[(32 + lane) * XL + i] = v2;
    }
    __syncthreads();

    // ---- layer 1: K=64, N=64 ----
    float acc[32];
    #pragma unroll
    for (int r = 0; r < 8; r++)
        #pragma unroll
        for (int c = 0; c < 4; c++) acc[r * 4 + c] = b1s[tx * 4 + c];

    #pragma unroll 4
    for (int k = 0; k < HID; k++) {
        float4 b  = *(const float4*)&W1s[k * HID + tx * 4];
        float4 a0 = *(const float4*)&xs[k * XL + ty * 8];
        float4 a1 = *(const float4*)&xs[k * XL + ty * 8 + 4];
        float a[8] = {a0.x, a0.y, a0.z, a0.w, a1.x, a1.y, a1.z, a1.w};
        #pragma unroll
        for (int r = 0; r < 8; r++) {
            acc[r * 4 + 0] = fmaf(a[r], b.x, acc[r * 4 + 0]);
            acc[r * 4 + 1] = fmaf(a[r], b.y, acc[r * 4 + 1]);
            acc[r * 4 + 2] = fmaf(a[r], b.z, acc[r * 4 + 2]);
            acc[r * 4 + 3] = fmaf(a[r], b.w, acc[r * 4 + 3]);
        }
    }
    __syncthreads();

    float* hs = xs;
    #pragma unroll
    for (int r = 0; r < 8; r++) {
        float4 v;
        v.x = fmaxf(acc[r * 4 + 0], 0.0f);
        v.y = fmaxf(acc[r * 4 + 1], 0.0f);
        v.z = fmaxf(acc[r * 4 + 2], 0.0f);
        v.w = fmaxf(acc[r * 4 + 3], 0.0f);
        *(float4*)&hs[(ty * 8 + r) * HL + tx * 4] = v;
    }
    __syncthreads();

    // ---- layer 2: K=64, N=64 ----
    #pragma unroll
    for (int r = 0; r < 8; r++)
        #pragma unroll
        for (int c = 0; c < 4; c++) acc[r * 4 + c] = b2s[tx * 4 + c];

    #pragma unroll 2
    for (int k = 0; k < HID; k++) {
        float4 b = *(const float4*)&W2s[k * HID + tx * 4];
        float a[8];
        #pragma unroll
        for (int r = 0; r < 8; r++) a[r] = hs[(ty * 8 + r) * HL + k];
        #pragma unroll
        for (int r = 0; r < 8; r++) {
            acc[r * 4 + 0] = fmaf(a[r], b.x, acc[r * 4 + 0]);
            acc[r * 4 + 1] = fmaf(a[r], b.y, acc[r * 4 + 1]);
            acc[r * 4 + 2] = fmaf(a[r], b.z, acc[r * 4 + 2]);
            acc[r * 4 + 3] = fmaf(a[r], b.w, acc[r * 4 + 3]);
        }
    }
    __syncthreads();

    #pragma unroll
    for (int r = 0; r < 8; r++) {
        float4 v;
        v.x = fmaxf(acc[r * 4 + 0], 0.0f);
        v.y = fmaxf(acc[r * 4 + 1], 0.0f);
        v.z = fmaxf(acc[r * 4 + 2], 0.0f);
        v.w = fmaxf(acc[r * 4 + 3], 0.0f);
        *(float4*)&hs[(ty * 8 + r) * HL + tx * 4] = v;
    }
    __syncthreads();

    // ---- layer 3: K=64, N=32 ----
    float acc3[16];
    #pragma unroll
    for (int r = 0; r < 8; r++) {
        acc3[r * 2 + 0] = b3s[tx * 2 + 0];
        acc3[r * 2 + 1] = b3s[tx * 2 + 1];
    }
    #pragma unroll 2
    for (int k = 0; k < HID; k++) {
        float2 b = *(const float2*)&W3s[k * F + tx * 2];
        float a[8];
        #pragma unroll
        for (int r = 0; r < 8; r++) a[r] = hs[(ty * 8 + r) * HL + k];
        #pragma unroll
        for (int r = 0; r < 8; r++) {
            acc3[r * 2 + 0] = fmaf(a[r], b.x, acc3[r * 2 + 0]);
            acc3[r * 2 + 1] = fmaf(a[r], b.y, acc3[r * 2 + 1]);
        }
    }

    #pragma unroll
    for (int r = 0; r < 8; r++) {
        int n = nbase + ty * 8 + r;
        if (n < NNODES) {
            float2 v;
            v.x = fmaxf(acc3[r * 2 + 0], 0.0f);
            v.y = fmaxf(acc3[r * 2 + 1], 0.0f);
            *(float2*)&u_nf[(size_t)n * F + tx * 2] = v;
        }
    }
}

extern "C" void kernel_launch(void* const* d_in, const int* in_sizes, int n_in,
                              void* d_out, int out_size)
{
    const float* nf  = (const float*)d_in[0];
    const float* ef  = (const float*)d_in[1];
    const int*   src = (const int*)  d_in[2];
    const int*   dst = (const int*)  d_in[3];
    const float* eW1 = (const float*)d_in[4];
    const float* eb1 = (const float*)d_in[5];
    const float* eW2 = (const float*)d_in[6];
    const float* eb2 = (const float*)d_in[7];
    const float* eW3 = (const float*)d_in[8];
    const float* eb3 = (const float*)d_in[9];
    const float* nW1 = (const float*)d_in[10];
    const float* nb1 = (const float*)d_in[11];
    const float* nW2 = (const float*)d_in[12];
    const float* nb2 = (const float*)d_in[13];
    const float* nW3 = (const float*)d_in[14];
    const float* nb3 = (const float*)d_in[15];

    float* out  = (float*)d_out;
    float* u_nf = out;                         // [NNODES, 32]
    float* u_ef = out + (size_t)NNODES * F;    // [NEDGES, 32]

    const int edge_smem = (96 * XL + 96 * HID + HID * HID + HID * F
                           + HID + HID + F) * (int)sizeof(float);   // ~100.3 KB
    const int node_smem = (128 * HL + HID * HID + HID * HID + HID * F
                           + HID + HID + F) * (int)sizeof(float);   // ~76 KB

    cudaFuncSetAttribute(edge_kernel, cudaFuncAttributeMaxDynamicSharedMemorySize, edge_smem);
    cudaFuncSetAttribute(node_kernel, cudaFuncAttributeMaxDynamicSharedMemorySize, node_smem);

    zero_agg_kernel<<<(NNODES * F + 255) / 256, 256>>>();

    edge_kernel<<<NEDGES / 128, 256, edge_smem>>>(
        nf, ef, src, dst, eW1, eb1, eW2, eb2, eW3, eb3, u_ef);

    node_kernel<<<(NNODES + 127) / 128, 256, node_smem>>>(
        nf, nW1, nb1, nW2, nb2, nW3, nb3, u_nf);
}